// round 1
// baseline (speedup 1.0000x reference)
#include <cuda_runtime.h>
#include <cstdint>

#define BB   64
#define TT   128
#define VV   10000
#define EE   300
#define HH   1024
#define G4   4096      // 4*H
#define TM1  127
#define MROWS 8128     // 127*64

// ---------------- scratch (static device globals; no allocation) ------------
__device__ float g_emb [MROWS * EE];          // [t*64+b][300]
__device__ float g_pre0[MROWS * G4];          // [t*64+b][4096]  x@w_ih0 + b0
__device__ float g_gp0 [8 * BB * G4];         // K-split partials, layer0
__device__ float g_gp1 [8 * BB * G4];         // K-split partials, layer1
__device__ float g_h0  [BB * HH];
__device__ float g_c0  [BB * HH];
__device__ float g_h1  [BB * HH];
__device__ float g_c1  [BB * HH];
__device__ float g_H1  [MROWS * HH];          // [b*127+t][1024]
__device__ float g_lossb[BB];

// ---------------- fast math (FMA-only exp; no MUFU) -------------------------
__device__ __forceinline__ float fexp(float x) {
    x = fminf(x, 88.0f);
    if (x < -87.0f) return 0.0f;
    float t = fmaf(x, 1.4426950408889634f, 12582912.0f);   // round(x*log2e) in low bits
    float n = t - 12582912.0f;
    int   e = __float_as_int(t) - 0x4B400000;
    float r = fmaf(n, -0.693359375f, x);                   // x - n*ln2 (hi/lo split)
    r = fmaf(n, 2.1219444e-4f, r);
    float p = fmaf(8.3333333e-3f, r, 4.1666668e-2f);
    p = fmaf(p, r, 1.6666667e-1f);
    p = fmaf(p, r, 0.5f);
    p = fmaf(p, r, 1.0f);
    p = fmaf(p, r, 1.0f);
    return __int_as_float(__float_as_int(p) + (e << 23));
}
__device__ __forceinline__ float sigf(float x)  { return 1.0f / (1.0f + fexp(-x)); }
__device__ __forceinline__ float tanhf_(float x){ return fmaf(2.0f, sigf(2.0f * x), -1.0f); }

// ---------------- init / gather ---------------------------------------------
__global__ void zero_state() {
    int idx = blockIdx.x * 256 + threadIdx.x;
    if (idx < BB * HH) { g_h0[idx] = 0.f; g_c0[idx] = 0.f; g_h1[idx] = 0.f; g_c1[idx] = 0.f; }
    if (idx < BB) g_lossb[idx] = 0.f;
}

__global__ void gather_emb(const int* __restrict__ sent, const float* __restrict__ wordvec) {
    int idx = blockIdx.x * 256 + threadIdx.x;
    if (idx >= MROWS * EE) return;
    int r = idx / EE, k = idx - r * EE;
    int t = r >> 6, b = r & 63;
    int w = sent[b * TT + t];
    g_emb[idx] = wordvec[(size_t)w * EE + k];
}

// ---------------- generic tiled SGEMM: C = A@B + bias (128x128x8, 8x8/thr) --
__global__ __launch_bounds__(256) void gemm128(
    int M, int N, int K,
    const float* __restrict__ A, int lda,
    const float* __restrict__ B, int ldb,
    const float* __restrict__ bias,
    float* __restrict__ C, int ldc)
{
    __shared__ float As[8][128];
    __shared__ float Bs[8][128];
    int tid = threadIdx.x;
    int tx = tid & 15, ty = tid >> 4;          // 16x16 -> 8x8 microtile
    int row0 = blockIdx.y * 128, col0 = blockIdx.x * 128;
    float acc[8][8];
#pragma unroll
    for (int i = 0; i < 8; i++)
#pragma unroll
        for (int j = 0; j < 8; j++) acc[i][j] = 0.f;

    for (int k0 = 0; k0 < K; k0 += 8) {
#pragma unroll
        for (int i = 0; i < 4; i++) {          // A tile 128x8
            int e = tid + i * 256;
            int r = e >> 3, kk = e & 7;
            int gr = row0 + r, gk = k0 + kk;
            float v = 0.f;
            if (gr < M && gk < K) v = A[(size_t)gr * lda + gk];
            As[kk][r] = v;
        }
#pragma unroll
        for (int i = 0; i < 4; i++) {          // B tile 8x128
            int e = tid + i * 256;
            int kk = e >> 7, c = e & 127;
            int gk = k0 + kk, gc = col0 + c;
            float v = 0.f;
            if (gk < K && gc < N) v = B[(size_t)gk * ldb + gc];
            Bs[kk][c] = v;
        }
        __syncthreads();
#pragma unroll
        for (int kk = 0; kk < 8; kk++) {
            float4 a0 = *(const float4*)&As[kk][ty * 8];
            float4 a1 = *(const float4*)&As[kk][ty * 8 + 4];
            float4 b0 = *(const float4*)&Bs[kk][tx * 8];
            float4 b1 = *(const float4*)&Bs[kk][tx * 8 + 4];
            float a[8] = {a0.x,a0.y,a0.z,a0.w,a1.x,a1.y,a1.z,a1.w};
            float b[8] = {b0.x,b0.y,b0.z,b0.w,b1.x,b1.y,b1.z,b1.w};
#pragma unroll
            for (int i = 0; i < 8; i++)
#pragma unroll
                for (int j = 0; j < 8; j++) acc[i][j] = fmaf(a[i], b[j], acc[i][j]);
        }
        __syncthreads();
    }
#pragma unroll
    for (int i = 0; i < 8; i++) {
        int gr = row0 + ty * 8 + i;
        if (gr >= M) continue;
#pragma unroll
        for (int j = 0; j < 8; j++) {
            int gc = col0 + tx * 8 + j;
            if (gc < N) C[(size_t)gr * ldc + gc] = acc[i][j] + bias[gc];
        }
    }
}

// ---------------- recurrent step GEMM: K-split partials ----------------------
// Cp[kc][64][4096] += A_half[64x1024 chunk] @ B_half[1024x4096 chunk]
__global__ __launch_bounds__(128) void gemm_step(
    const float* __restrict__ Aa, const float* __restrict__ Ba,
    const float* __restrict__ Ab, const float* __restrict__ Bb,
    int half, int csize, float* __restrict__ Cp)
{
    int kc = blockIdx.y;
    const float* A = (kc < half) ? Aa : Ab;
    const float* B = (kc < half) ? Ba : Bb;
    int k0 = ((kc < half) ? kc : kc - half) * csize;

    __shared__ float As[8][64];
    __shared__ float Bs[8][128];
    int tid = threadIdx.x;
    int tx = tid & 15, ty = tid >> 4;          // 16x8 -> 8x8 microtile (64x128 tile)
    int col0 = blockIdx.x * 128;
    float acc[8][8];
#pragma unroll
    for (int i = 0; i < 8; i++)
#pragma unroll
        for (int j = 0; j < 8; j++) acc[i][j] = 0.f;

    for (int kt = 0; kt < csize; kt += 8) {
        int kb = k0 + kt;
#pragma unroll
        for (int i = 0; i < 4; i++) {          // A tile 64x8
            int e = tid + i * 128;
            int r = e >> 3, kk = e & 7;
            As[kk][r] = A[r * HH + kb + kk];
        }
#pragma unroll
        for (int i = 0; i < 8; i++) {          // B tile 8x128
            int e = tid + i * 128;
            int kk = e >> 7, c = e & 127;
            Bs[kk][c] = B[(size_t)(kb + kk) * G4 + col0 + c];
        }
        __syncthreads();
#pragma unroll
        for (int kk = 0; kk < 8; kk++) {
            float4 a0 = *(const float4*)&As[kk][ty * 8];
            float4 a1 = *(const float4*)&As[kk][ty * 8 + 4];
            float4 b0 = *(const float4*)&Bs[kk][tx * 8];
            float4 b1 = *(const float4*)&Bs[kk][tx * 8 + 4];
            float a[8] = {a0.x,a0.y,a0.z,a0.w,a1.x,a1.y,a1.z,a1.w};
            float b[8] = {b0.x,b0.y,b0.z,b0.w,b1.x,b1.y,b1.z,b1.w};
#pragma unroll
            for (int i = 0; i < 8; i++)
#pragma unroll
                for (int j = 0; j < 8; j++) acc[i][j] = fmaf(a[i], b[j], acc[i][j]);
        }
        __syncthreads();
    }
#pragma unroll
    for (int i = 0; i < 8; i++) {
        int row = ty * 8 + i;
        size_t base = ((size_t)(kc * 64 + row)) * G4 + col0 + tx * 8;
        float4 v0 = {acc[i][0], acc[i][1], acc[i][2], acc[i][3]};
        float4 v1 = {acc[i][4], acc[i][5], acc[i][6], acc[i][7]};
        *(float4*)&Cp[base]     = v0;
        *(float4*)&Cp[base + 4] = v1;
    }
}

// ---------------- LSTM elementwise updates ----------------------------------
__global__ __launch_bounds__(256) void upd0(int t) {
    int idx = blockIdx.x * 256 + threadIdx.x;  // 65536
    int b = idx >> 10, h = idx & 1023;
    const float* pre = g_pre0 + ((size_t)(t * 64 + b)) * G4;
    float gi = pre[h], gf = pre[HH + h], gg = pre[2 * HH + h], go = pre[3 * HH + h];
#pragma unroll
    for (int kc = 0; kc < 8; kc++) {
        const float* gp = g_gp0 + ((size_t)(kc * 64 + b)) * G4;
        gi += gp[h]; gf += gp[HH + h]; gg += gp[2 * HH + h]; go += gp[3 * HH + h];
    }
    float c = sigf(gf) * g_c0[idx] + sigf(gi) * tanhf_(gg);
    float hn = sigf(go) * tanhf_(c);
    g_c0[idx] = c;
    g_h0[idx] = hn;
}

__global__ __launch_bounds__(256) void upd1(int t, const float* __restrict__ b1) {
    int idx = blockIdx.x * 256 + threadIdx.x;
    int b = idx >> 10, h = idx & 1023;
    float gi = b1[h], gf = b1[HH + h], gg = b1[2 * HH + h], go = b1[3 * HH + h];
#pragma unroll
    for (int kc = 0; kc < 8; kc++) {
        const float* gp = g_gp1 + ((size_t)(kc * 64 + b)) * G4;
        gi += gp[h]; gf += gp[HH + h]; gg += gp[2 * HH + h]; go += gp[3 * HH + h];
    }
    float c = sigf(gf) * g_c1[idx] + sigf(gi) * tanhf_(gg);
    float hn = sigf(go) * tanhf_(c);
    g_c1[idx] = c;
    g_h1[idx] = hn;
    g_H1[((size_t)b * TM1 + t) * HH + h] = hn;   // output-GEMM row ordering b*127+t
}

// ---------------- loss: per-(b,t) log-softmax + gather -----------------------
__global__ __launch_bounds__(256) void loss_row(const float* __restrict__ temp,
                                                const int* __restrict__ sent) {
    int t = blockIdx.x, b = blockIdx.y;
    const float* lg = temp + ((size_t)b * TM1 + t) * VV;
    __shared__ float buf[VV];
    __shared__ float red[8];
    __shared__ float s_mx;
    int tid = threadIdx.x;
    for (int i = tid; i < VV; i += 256) buf[i] = lg[i];
    __syncthreads();
    float m = -3.4e38f;
    for (int i = tid; i < VV; i += 256) m = fmaxf(m, buf[i]);
#pragma unroll
    for (int o = 16; o; o >>= 1) m = fmaxf(m, __shfl_xor_sync(0xffffffffu, m, o));
    if ((tid & 31) == 0) red[tid >> 5] = m;
    __syncthreads();
    if (tid == 0) {
        float v = red[0];
        for (int i = 1; i < 8; i++) v = fmaxf(v, red[i]);
        s_mx = v;
    }
    __syncthreads();
    float mx = s_mx;
    float s = 0.f;
    for (int i = tid; i < VV; i += 256) s += fexp(buf[i] - mx);
#pragma unroll
    for (int o = 16; o; o >>= 1) s += __shfl_xor_sync(0xffffffffu, s, o);
    if ((tid & 31) == 0) red[tid >> 5] = s;
    __syncthreads();
    if (tid == 0) {
        float v = 0.f;
        for (int i = 0; i < 8; i++) v += red[i];
        int gt = sent[b * TT + t + 1];
        if (gt != 0) {
            float lp = buf[gt] - (mx + logf(v));
            atomicAdd(&g_lossb[b], lp);
        }
    }
}

__global__ void loss_final(const int* __restrict__ length, float* __restrict__ out) {
    int tid = threadIdx.x;  // 64 threads
    float v = -g_lossb[tid] / (float)length[tid];
#pragma unroll
    for (int o = 16; o; o >>= 1) v += __shfl_xor_sync(0xffffffffu, v, o);
    __shared__ float r2[2];
    if ((tid & 31) == 0) r2[tid >> 5] = v;
    __syncthreads();
    if (tid == 0) out[0] = r2[0] + r2[1];
}

// ---------------- launch ------------------------------------------------------
extern "C" void kernel_launch(void* const* d_in, const int* in_sizes, int n_in,
                              void* d_out, int out_size) {
    const int*   sent    = (const int*)  d_in[0];
    const int*   length  = (const int*)  d_in[1];
    const float* wordvec = (const float*)d_in[2];
    const float* w_ih0   = (const float*)d_in[3];
    const float* w_hh0   = (const float*)d_in[4];
    const float* b0      = (const float*)d_in[5];
    const float* w_ih1   = (const float*)d_in[6];
    const float* w_hh1   = (const float*)d_in[7];
    const float* b1      = (const float*)d_in[8];
    const float* w_out   = (const float*)d_in[9];
    const float* b_out   = (const float*)d_in[10];
    float* out = (float*)d_out;

    long long tempoff = (long long)out_size - (long long)MROWS * VV;  // expected 1 (loss first)
    if (tempoff < 0) tempoff = 0;
    float* temp = out + tempoff;

    float *p_emb, *p_pre0, *p_gp0, *p_gp1, *p_h0, *p_h1, *p_H1;
    cudaGetSymbolAddress((void**)&p_emb,  g_emb);
    cudaGetSymbolAddress((void**)&p_pre0, g_pre0);
    cudaGetSymbolAddress((void**)&p_gp0,  g_gp0);
    cudaGetSymbolAddress((void**)&p_gp1,  g_gp1);
    cudaGetSymbolAddress((void**)&p_h0,   g_h0);
    cudaGetSymbolAddress((void**)&p_h1,   g_h1);
    cudaGetSymbolAddress((void**)&p_H1,   g_H1);

    zero_state<<<256, 256>>>();
    gather_emb<<<(MROWS * EE + 255) / 256, 256>>>(sent, wordvec);

    // pre0 = emb @ w_ih0 + b0   [8128,300]@[300,4096]
    gemm128<<<dim3(G4 / 128, (MROWS + 127) / 128), 256>>>(
        MROWS, G4, EE, p_emb, EE, w_ih0, G4, b0, p_pre0, G4);

    for (int t = 0; t < TM1; t++) {
        // layer0: gp0 = h0 @ w_hh0  (8 K-chunks of 128)
        gemm_step<<<dim3(32, 8), 128>>>(p_h0, w_hh0, p_h0, w_hh0, 8, 128, p_gp0);
        upd0<<<256, 256>>>(t);
        // layer1: gp1 = [h0|h1] @ [w_ih1; w_hh1]  (4+4 K-chunks of 256)
        gemm_step<<<dim3(32, 8), 128>>>(p_h0, w_ih1, p_h1, w_hh1, 4, 256, p_gp1);
        upd1<<<256, 256>>>(t, b1);
    }

    // logits = H1 @ w_out + b_out  [8128,1024]@[1024,10000]
    gemm128<<<dim3((VV + 127) / 128, (MROWS + 127) / 128), 256>>>(
        MROWS, VV, HH, p_H1, HH, w_out, VV, b_out, temp, VV);

    loss_row<<<dim3(TM1, BB), 256>>>(temp, sent);
    if (tempoff > 0) loss_final<<<1, 64>>>(length, out);
}

// round 3
// speedup vs baseline: 3.4973x; 3.4973x over previous
#include <cuda_runtime.h>
#include <cuda_bf16.h>
#include <cstdint>

#define BB   64
#define TT   128
#define VV   10000
#define EE   300
#define HH   1024
#define G4   4096
#define TM1  127
#define MROWS 8128
#define KE   320        // padded E
#define NPADV 10112     // padded V (79*128)

typedef __nv_bfloat16 bf16;

// ---------------- scratch (device globals) -----------------------------------
__device__ __align__(16) bf16  g_embH[MROWS * KE];
__device__ __align__(16) bf16  g_embL[MROWS * KE];
__device__ __align__(16) float g_pre0[(size_t)MROWS * G4];
__device__ __align__(16) float g_gp0 [4 * BB * G4];
__device__ __align__(16) float g_gp1 [4 * BB * G4];
__device__ __align__(16) float g_c0  [BB * HH];
__device__ __align__(16) float g_c1  [BB * HH];
__device__ __align__(16) bf16  g_AbufH[BB * 2048];    // [64][h0|h1]
__device__ __align__(16) bf16  g_AbufL[BB * 2048];
__device__ __align__(16) bf16  g_H1H[(size_t)MROWS * HH];
__device__ __align__(16) bf16  g_H1L[(size_t)MROWS * HH];
__device__ __align__(16) bf16  g_wih0TH[G4 * KE],  g_wih0TL[G4 * KE];      // [4096][320]
__device__ __align__(16) bf16  g_whh0TH[G4 * HH],  g_whh0TL[G4 * HH];      // [4096][1024]
__device__ __align__(16) bf16  g_w1TH [G4 * 2048], g_w1TL [G4 * 2048];     // [4096][2048]
__device__ __align__(16) bf16  g_woutTH[(size_t)NPADV * HH], g_woutTL[(size_t)NPADV * HH];
__device__ float g_lossb[BB];

// ---------------- fast math (FMA-only exp) -----------------------------------
__device__ __forceinline__ float fexp(float x) {
    x = fminf(x, 88.0f);
    if (x < -87.0f) return 0.0f;
    float t = fmaf(x, 1.4426950408889634f, 12582912.0f);
    float n = t - 12582912.0f;
    int   e = __float_as_int(t) - 0x4B400000;
    float r = fmaf(n, -0.693359375f, x);
    r = fmaf(n, 2.1219444e-4f, r);
    float p = fmaf(8.3333333e-3f, r, 4.1666668e-2f);
    p = fmaf(p, r, 1.6666667e-1f);
    p = fmaf(p, r, 0.5f);
    p = fmaf(p, r, 1.0f);
    p = fmaf(p, r, 1.0f);
    return __int_as_float(__float_as_int(p) + (e << 23));
}
__device__ __forceinline__ float sigf(float x)  { return 1.0f / (1.0f + fexp(-x)); }
__device__ __forceinline__ float tanhf_(float x){ return fmaf(2.0f, sigf(2.0f * x), -1.0f); }

// ---------------- ptx helpers (sm_80-class: cp.async/ldmatrix/mma.sync) ------
__device__ __forceinline__ uint32_t smem_u32(const void* p) {
    uint32_t a;
    asm("{ .reg .u64 t; cvta.to.shared.u64 t, %1; cvt.u32.u64 %0, t; }" : "=r"(a) : "l"(p));
    return a;
}
__device__ __forceinline__ void cpa16(uint32_t dst, const void* src, int valid) {
    asm volatile("cp.async.cg.shared.global [%0], [%1], 16, %2;"
                 :: "r"(dst), "l"(src), "r"(valid) : "memory");
}
#define CP_COMMIT()  asm volatile("cp.async.commit_group;" ::: "memory")
#define CP_WAIT(n)   asm volatile("cp.async.wait_group %0;" :: "n"(n) : "memory")

__device__ __forceinline__ void ldm4(uint32_t* r, uint32_t addr) {
    asm volatile("ldmatrix.sync.aligned.m8n8.x4.shared.b16 {%0,%1,%2,%3}, [%4];"
                 : "=r"(r[0]), "=r"(r[1]), "=r"(r[2]), "=r"(r[3]) : "r"(addr));
}
__device__ __forceinline__ void mma16816(float* d, const uint32_t* a, const uint32_t* b) {
    asm volatile(
        "mma.sync.aligned.m16n8k16.row.col.f32.bf16.bf16.f32 "
        "{%0,%1,%2,%3}, {%4,%5,%6,%7}, {%8,%9}, {%0,%1,%2,%3};"
        : "+f"(d[0]), "+f"(d[1]), "+f"(d[2]), "+f"(d[3])
        : "r"(a[0]), "r"(a[1]), "r"(a[2]), "r"(a[3]), "r"(b[0]), "r"(b[1]));
}
#define SW128(x) ((x) ^ (((x) >> 3) & 0x70))

// ---------------- init / gather / prep ---------------------------------------
__global__ void zero_state() {
    int idx = blockIdx.x * 256 + threadIdx.x;        // 131072 threads
    int b = idx >> 11, j = idx & 2047;
    bf16 z = __float2bfloat16_rn(0.0f);
    g_AbufH[idx] = z;
    g_AbufL[idx] = z;
    if (j < 1024) { g_c0[b * 1024 + j] = 0.f; g_c1[b * 1024 + j] = 0.f; }
    if (idx < BB) g_lossb[idx] = 0.f;
}

__global__ void gather_emb(const int* __restrict__ sent, const float* __restrict__ wordvec) {
    int idx = blockIdx.x * 256 + threadIdx.x;
    if (idx >= MROWS * KE) return;
    int r = idx / KE, k = idx - r * KE;
    int t = r >> 6, b = r & 63;
    float v = 0.f;
    if (k < EE) { int w = sent[b * TT + t]; v = wordvec[(size_t)w * EE + k]; }
    bf16 hi = __float2bfloat16_rn(v);
    g_embH[idx] = hi;
    g_embL[idx] = __float2bfloat16_rn(v - __bfloat162float(hi));
}

// transpose + split: W fp32 [Ksrc, Nsrc] -> Oh/Ol bf16 [Npad][Kpad] at col offset koff
__global__ void prep_T(const float* __restrict__ W, int Ksrc, int Nsrc,
                       bf16* __restrict__ Oh, bf16* __restrict__ Ol,
                       int Kpad, int koff, int Kspan, int Npad) {
    __shared__ float ts[32][33];
    int k0 = blockIdx.x * 32, n0 = blockIdx.y * 32;
    int tx = threadIdx.x, ty = threadIdx.y;
#pragma unroll
    for (int i = 0; i < 4; i++) {
        int k = k0 + ty + i * 8, n = n0 + tx;
        float v = (k < Ksrc && n < Nsrc) ? W[(size_t)k * Nsrc + n] : 0.f;
        ts[ty + i * 8][tx] = v;
    }
    __syncthreads();
#pragma unroll
    for (int i = 0; i < 4; i++) {
        int n = n0 + ty + i * 8, k = k0 + tx;
        if (n < Npad && k < Kspan) {
            float v = ts[tx][ty + i * 8];
            bf16 hi = __float2bfloat16_rn(v);
            size_t o = (size_t)n * Kpad + koff + k;
            Oh[o] = hi;
            Ol[o] = __float2bfloat16_rn(v - __bfloat162float(hi));
        }
    }
}

// ---------------- bf16x2-split GEMM via mma.sync ------------------------------
// C[M,N] = (Ah+Al)[M,K] @ (Bh+Bl)^T[N,K]   (A row-major [M][K], B stored [N][K])
// MT=2: CTA tile 128x128 (warps 2x4).  MT=1: CTA tile 64x128 (warps 1x8).
// mode 0: C[row*ldc+col] = acc + bias[col]  (row<Mreal, col<Nreal)
// mode 1: C[(z*64*MT+row)*ldc + col] = acc  (K-split partials)
template<int MT>
__device__ __forceinline__ void ldstage(
    uint32_t st, int tid, int m0, int n0, int k0,
    const bf16* Ah, const bf16* Al, int lda,
    const bf16* Bh, const bf16* Bl, int ldb, int Mreal)
{
    constexpr int AROWS  = MT * 64;
    constexpr int OFF_AL = AROWS * 128;
    constexpr int OFF_B  = AROWS * 256;
#pragma unroll
    for (int e = tid; e < AROWS * 8; e += 256) {
        int r = e >> 3, c = e & 7;
        uint32_t sw = SW128((uint32_t)(r * 128 + c * 16));
        int gr = m0 + r;
        int ok = 16;
        if (MT == 2 && gr >= Mreal) { ok = 0; gr = 0; }
        size_t off = (size_t)gr * lda + k0 + c * 8;
        cpa16(st + sw,          Ah + off, ok);
        cpa16(st + OFF_AL + sw, Al + off, ok);
    }
#pragma unroll
    for (int e = tid; e < 1024; e += 256) {
        int r = e >> 3, c = e & 7;
        uint32_t sw = SW128((uint32_t)(r * 128 + c * 16));
        size_t off = (size_t)(n0 + r) * ldb + k0 + c * 8;
        cpa16(st + OFF_B + sw,          Bh + off, 16);
        cpa16(st + OFF_B + 16384 + sw,  Bl + off, 16);
    }
}

template<int MT>
__global__ __launch_bounds__(256, 1) void gemm_mma(
    const bf16* __restrict__ Ah, const bf16* __restrict__ Al, int lda,
    const bf16* __restrict__ Bh, const bf16* __restrict__ Bl, int ldb,
    int kPerSplit, int Mreal, int Nreal,
    const float* __restrict__ bias, float* __restrict__ C, int ldc, int mode)
{
    extern __shared__ char smem[];
    constexpr int AROWS  = MT * 64;
    constexpr int OFF_AL = AROWS * 128;
    constexpr int OFF_B  = AROWS * 256;
    constexpr int STAGE  = AROWS * 256 + 32768;
    constexpr int NW     = MT * 16;          // warp n-width
    constexpr int NT     = 2 * MT;           // n8 tiles per warp

    int tid = threadIdx.x, lane = tid & 31, wid = tid >> 5;
    int wm = (MT == 2) ? (wid & 1) : 0;
    int wn = (MT == 2) ? (wid >> 1) : wid;
    int n0 = blockIdx.x * 128, m0 = blockIdx.y * AROWS;
    int kstart = blockIdx.z * kPerSplit;
    int nch = kPerSplit >> 6;

    uint32_t sb = smem_u32(smem);
    float acc[4][NT][4];
#pragma unroll
    for (int i = 0; i < 4; i++)
#pragma unroll
        for (int j = 0; j < NT; j++)
#pragma unroll
            for (int v = 0; v < 4; v++) acc[i][j][v] = 0.f;

    ldstage<MT>(sb, tid, m0, n0, kstart, Ah, Al, lda, Bh, Bl, ldb, Mreal);
    CP_COMMIT();

    for (int ic = 0; ic < nch; ic++) {
        uint32_t st = sb + (uint32_t)(ic & 1) * STAGE;
        if (ic + 1 < nch) {
            ldstage<MT>(sb + (uint32_t)((ic + 1) & 1) * STAGE, tid, m0, n0,
                        kstart + (ic + 1) * 64, Ah, Al, lda, Bh, Bl, ldb, Mreal);
            CP_COMMIT();
            CP_WAIT(1);
        } else {
            CP_WAIT(0);
        }
        __syncthreads();

#pragma unroll
        for (int q = 0; q < 4; q++) {
            uint32_t ah[4][4], al[4][4];
            int arow = wm * 64 + (lane & 15);
            int ach  = q * 32 + ((lane >> 4) << 4);
#pragma unroll
            for (int mt = 0; mt < 4; mt++) {
                uint32_t loc = SW128((uint32_t)((arow + mt * 16) * 128 + ach));
                ldm4(ah[mt], st + loc);
                ldm4(al[mt], st + OFF_AL + loc);
            }
            uint32_t bh[MT][4], bl[MT][4];
            int brow = wn * NW + (lane & 7) + (((lane >> 4) & 1) << 3);
            int bch  = q * 32 + (((lane >> 3) & 1) << 4);
#pragma unroll
            for (int p = 0; p < MT; p++) {
                uint32_t loc = SW128((uint32_t)((brow + p * 16) * 128 + bch));
                ldm4(bh[p], st + OFF_B + loc);
                ldm4(bl[p], st + OFF_B + 16384 + loc);
            }
#pragma unroll
            for (int mt = 0; mt < 4; mt++)
#pragma unroll
                for (int p = 0; p < MT; p++)
#pragma unroll
                    for (int h = 0; h < 2; h++) {
                        int nt = p * 2 + h;
                        mma16816(acc[mt][nt], ah[mt], &bh[p][h * 2]);
                        mma16816(acc[mt][nt], ah[mt], &bl[p][h * 2]);
                        mma16816(acc[mt][nt], al[mt], &bh[p][h * 2]);
                    }
        }
        __syncthreads();
    }

    // epilogue
    int rbase = (mode ? blockIdx.z * AROWS : m0) + wm * 64 + (lane >> 2);
    int cbase = n0 + wn * NW + (lane & 3) * 2;
#pragma unroll
    for (int mt = 0; mt < 4; mt++)
#pragma unroll
        for (int nt = 0; nt < NT; nt++) {
            int col = cbase + nt * 8;
            int r0 = rbase + mt * 16;
            if (mode == 0) {
                if (col < Nreal) {
                    float ba = bias[col], bb = bias[col + 1];
                    if (r0 < Mreal) {
                        C[(size_t)r0 * ldc + col]     = acc[mt][nt][0] + ba;
                        C[(size_t)r0 * ldc + col + 1] = acc[mt][nt][1] + bb;
                    }
                    if (r0 + 8 < Mreal) {
                        C[(size_t)(r0 + 8) * ldc + col]     = acc[mt][nt][2] + ba;
                        C[(size_t)(r0 + 8) * ldc + col + 1] = acc[mt][nt][3] + bb;
                    }
                }
            } else {
                C[(size_t)r0 * ldc + col]           = acc[mt][nt][0];
                C[(size_t)r0 * ldc + col + 1]       = acc[mt][nt][1];
                C[(size_t)(r0 + 8) * ldc + col]     = acc[mt][nt][2];
                C[(size_t)(r0 + 8) * ldc + col + 1] = acc[mt][nt][3];
            }
        }
}

// ---------------- LSTM elementwise updates -----------------------------------
__global__ __launch_bounds__(256) void upd0(int t) {
    int idx = blockIdx.x * 256 + threadIdx.x;   // 65536
    int b = idx >> 10, h = idx & 1023;
    const float* pre = g_pre0 + ((size_t)(t * 64 + b)) * G4;
    float gi = pre[h], gf = pre[1024 + h], gg = pre[2048 + h], go = pre[3072 + h];
#pragma unroll
    for (int z = 0; z < 4; z++) {
        const float* gp = g_gp0 + ((size_t)(z * 64 + b)) * G4;
        gi += gp[h]; gf += gp[1024 + h]; gg += gp[2048 + h]; go += gp[3072 + h];
    }
    float c = sigf(gf) * g_c0[idx] + sigf(gi) * tanhf_(gg);
    float hn = sigf(go) * tanhf_(c);
    g_c0[idx] = c;
    bf16 hi = __float2bfloat16_rn(hn);
    g_AbufH[b * 2048 + h] = hi;
    g_AbufL[b * 2048 + h] = __float2bfloat16_rn(hn - __bfloat162float(hi));
}

__global__ __launch_bounds__(256) void upd1(int t, const float* __restrict__ b1) {
    int idx = blockIdx.x * 256 + threadIdx.x;
    int b = idx >> 10, h = idx & 1023;
    float gi = b1[h], gf = b1[1024 + h], gg = b1[2048 + h], go = b1[3072 + h];
#pragma unroll
    for (int z = 0; z < 4; z++) {
        const float* gp = g_gp1 + ((size_t)(z * 64 + b)) * G4;
        gi += gp[h]; gf += gp[1024 + h]; gg += gp[2048 + h]; go += gp[3072 + h];
    }
    float c = sigf(gf) * g_c1[idx] + sigf(gi) * tanhf_(gg);
    float hn = sigf(go) * tanhf_(c);
    g_c1[idx] = c;
    bf16 hi = __float2bfloat16_rn(hn);
    bf16 lo = __float2bfloat16_rn(hn - __bfloat162float(hi));
    g_AbufH[b * 2048 + 1024 + h] = hi;
    g_AbufL[b * 2048 + 1024 + h] = lo;
    size_t o = ((size_t)b * TM1 + t) * HH + h;
    g_H1H[o] = hi;
    g_H1L[o] = lo;
}

// ---------------- loss --------------------------------------------------------
__global__ __launch_bounds__(256) void loss_row(const float* __restrict__ temp,
                                                const int* __restrict__ sent) {
    int t = blockIdx.x, b = blockIdx.y;
    const float* lg = temp + ((size_t)b * TM1 + t) * VV;
    __shared__ float buf[VV];
    __shared__ float red[8];
    __shared__ float s_mx;
    int tid = threadIdx.x;
    for (int i = tid; i < VV; i += 256) buf[i] = lg[i];
    __syncthreads();
    float m = -3.4e38f;
    for (int i = tid; i < VV; i += 256) m = fmaxf(m, buf[i]);
#pragma unroll
    for (int o = 16; o; o >>= 1) m = fmaxf(m, __shfl_xor_sync(0xffffffffu, m, o));
    if ((tid & 31) == 0) red[tid >> 5] = m;
    __syncthreads();
    if (tid == 0) {
        float v = red[0];
        for (int i = 1; i < 8; i++) v = fmaxf(v, red[i]);
        s_mx = v;
    }
    __syncthreads();
    float mx = s_mx;
    float s = 0.f;
    for (int i = tid; i < VV; i += 256) s += fexp(buf[i] - mx);
#pragma unroll
    for (int o = 16; o; o >>= 1) s += __shfl_xor_sync(0xffffffffu, s, o);
    if ((tid & 31) == 0) red[tid >> 5] = s;
    __syncthreads();
    if (tid == 0) {
        float v = 0.f;
        for (int i = 0; i < 8; i++) v += red[i];
        int gt = sent[b * TT + t + 1];
        if (gt != 0) {
            float lp = buf[gt] - (mx + logf(v));
            atomicAdd(&g_lossb[b], lp);
        }
    }
}

__global__ void loss_final(const int* __restrict__ length, float* __restrict__ out) {
    int tid = threadIdx.x;  // 64 threads
    float v = -g_lossb[tid] / (float)length[tid];
#pragma unroll
    for (int o = 16; o; o >>= 1) v += __shfl_xor_sync(0xffffffffu, v, o);
    __shared__ float r2[2];
    if ((tid & 31) == 0) r2[tid >> 5] = v;
    __syncthreads();
    if (tid == 0) out[0] = r2[0] + r2[1];
}

// ---------------- launch ------------------------------------------------------
#define SMEM1 98304    // MT=1: 2 * (64*256 + 32768)
#define SMEM2 131072   // MT=2: 2 * (128*256 + 32768)

extern "C" void kernel_launch(void* const* d_in, const int* in_sizes, int n_in,
                              void* d_out, int out_size) {
    const int*   sent    = (const int*)  d_in[0];
    const int*   length  = (const int*)  d_in[1];
    const float* wordvec = (const float*)d_in[2];
    const float* w_ih0   = (const float*)d_in[3];
    const float* w_hh0   = (const float*)d_in[4];
    const float* b0      = (const float*)d_in[5];
    const float* w_ih1   = (const float*)d_in[6];
    const float* w_hh1   = (const float*)d_in[7];
    const float* b1      = (const float*)d_in[8];
    const float* w_out   = (const float*)d_in[9];
    const float* b_out   = (const float*)d_in[10];
    float* out = (float*)d_out;

    long long tempoff = (long long)out_size - (long long)MROWS * VV;
    if (tempoff < 0) tempoff = 0;
    float* temp = out + tempoff;

    static int smem_set = 0;
    if (!smem_set) {
        cudaFuncSetAttribute(gemm_mma<1>, cudaFuncAttributeMaxDynamicSharedMemorySize, SMEM1);
        cudaFuncSetAttribute(gemm_mma<2>, cudaFuncAttributeMaxDynamicSharedMemorySize, SMEM2);
        smem_set = 1;
    }

    float *p_pre0, *p_gp0, *p_gp1;
    bf16 *p_embH, *p_embL, *p_AbH, *p_AbL, *p_H1H, *p_H1L;
    bf16 *p_wih0H, *p_wih0L, *p_whh0H, *p_whh0L, *p_w1H, *p_w1L, *p_woH, *p_woL;
    cudaGetSymbolAddress((void**)&p_pre0, g_pre0);
    cudaGetSymbolAddress((void**)&p_gp0,  g_gp0);
    cudaGetSymbolAddress((void**)&p_gp1,  g_gp1);
    cudaGetSymbolAddress((void**)&p_embH, g_embH);
    cudaGetSymbolAddress((void**)&p_embL, g_embL);
    cudaGetSymbolAddress((void**)&p_AbH,  g_AbufH);
    cudaGetSymbolAddress((void**)&p_AbL,  g_AbufL);
    cudaGetSymbolAddress((void**)&p_H1H,  g_H1H);
    cudaGetSymbolAddress((void**)&p_H1L,  g_H1L);
    cudaGetSymbolAddress((void**)&p_wih0H, g_wih0TH);
    cudaGetSymbolAddress((void**)&p_wih0L, g_wih0TL);
    cudaGetSymbolAddress((void**)&p_whh0H, g_whh0TH);
    cudaGetSymbolAddress((void**)&p_whh0L, g_whh0TL);
    cudaGetSymbolAddress((void**)&p_w1H,  g_w1TH);
    cudaGetSymbolAddress((void**)&p_w1L,  g_w1TL);
    cudaGetSymbolAddress((void**)&p_woH,  g_woutTH);
    cudaGetSymbolAddress((void**)&p_woL,  g_woutTL);

    zero_state<<<512, 256>>>();
    gather_emb<<<(MROWS * KE + 255) / 256, 256>>>(sent, wordvec);

    dim3 pth(32, 8);
    prep_T<<<dim3(KE / 32, G4 / 32), pth>>>(w_ih0, EE, G4, p_wih0H, p_wih0L, KE, 0, KE, G4);
    prep_T<<<dim3(HH / 32, G4 / 32), pth>>>(w_hh0, HH, G4, p_whh0H, p_whh0L, HH, 0, HH, G4);
    prep_T<<<dim3(HH / 32, G4 / 32), pth>>>(w_ih1, HH, G4, p_w1H, p_w1L, 2048, 0, HH, G4);
    prep_T<<<dim3(HH / 32, G4 / 32), pth>>>(w_hh1, HH, G4, p_w1H, p_w1L, 2048, 1024, HH, G4);
    prep_T<<<dim3(HH / 32, NPADV / 32), pth>>>(w_out, HH, VV, p_woH, p_woL, HH, 0, HH, NPADV);

    // pre0 = emb @ w_ih0 + b0   [8128,320pad]@[320,4096]
    gemm_mma<2><<<dim3(G4 / 128, 64, 1), 256, SMEM2>>>(
        p_embH, p_embL, KE, p_wih0H, p_wih0L, KE, KE, MROWS, G4, b0, p_pre0, G4, 0);

    for (int t = 0; t < TM1; t++) {
        // layer0: gp0[z] = h0 @ w_hh0 (K-split 4 x 256)
        gemm_mma<1><<<dim3(32, 1, 4), 256, SMEM1>>>(
            p_AbH, p_AbL, 2048, p_whh0H, p_whh0L, HH, 256, 64, G4, nullptr, p_gp0, G4, 1);
        upd0<<<256, 256>>>(t);
        // layer1: gp1[z] = [h0|h1] @ [w_ih1;w_hh1] (K-split 4 x 512)
        gemm_mma<1><<<dim3(32, 1, 4), 256, SMEM1>>>(
            p_AbH, p_AbL, 2048, p_w1H, p_w1L, 2048, 512, 64, G4, nullptr, p_gp1, G4, 1);
        upd1<<<256, 256>>>(t, b1);
    }

    // logits = H1 @ w_out + b_out  [8128,1024]@[1024,10000pad]
    gemm_mma<2><<<dim3(NPADV / 128, 64, 1), 256, SMEM2>>>(
        p_H1H, p_H1L, HH, p_woH, p_woL, HH, HH, MROWS, VV, b_out, temp, VV, 0);

    loss_row<<<dim3(TM1, BB), 256>>>(temp, sent);
    if (tempoff > 0) loss_final<<<1, 64>>>(length, out);
}

// round 4
// speedup vs baseline: 4.5659x; 1.3056x over previous
#include <cuda_runtime.h>
#include <cuda_fp16.h>
#include <cstdint>

#define BB   64
#define TT   128
#define VV   10000
#define EE   300
#define HH   1024
#define G4   4096
#define TM1  127
#define MROWS 8128
#define KE   320        // padded E
#define NPADV 10112     // padded V (79*128)

typedef __half fp16;

// ---------------- scratch (device globals) -----------------------------------
__device__ __align__(16) fp16  g_emb [MROWS * KE];
__device__ __align__(16) float g_pre0[(size_t)MROWS * G4];
__device__ __align__(16) float g_gp0 [4 * BB * G4];
__device__ __align__(16) float g_gp1 [4 * BB * G4];
__device__ __align__(16) float g_c0  [BB * HH];
__device__ __align__(16) float g_c1  [BB * HH];
__device__ __align__(16) fp16  g_AbufH[BB * 2048];    // [64][h0|h1] hi
__device__ __align__(16) fp16  g_AbufL[BB * 2048];    // lo residual
__device__ __align__(16) fp16  g_H1  [(size_t)MROWS * HH];
__device__ __align__(16) fp16  g_wih0T[G4 * KE];                  // [4096][320]
__device__ __align__(16) fp16  g_whh0T[G4 * HH];                  // [4096][1024]
__device__ __align__(16) fp16  g_w1T [G4 * 2048];                 // [4096][2048]
__device__ __align__(16) fp16  g_woutT[(size_t)NPADV * HH];       // [10112][1024]
__device__ float g_lossb[BB];

// ---------------- fast math (FMA-only exp) -----------------------------------
__device__ __forceinline__ float fexp(float x) {
    x = fminf(x, 88.0f);
    if (x < -87.0f) return 0.0f;
    float t = fmaf(x, 1.4426950408889634f, 12582912.0f);
    float n = t - 12582912.0f;
    int   e = __float_as_int(t) - 0x4B400000;
    float r = fmaf(n, -0.693359375f, x);
    r = fmaf(n, 2.1219444e-4f, r);
    float p = fmaf(8.3333333e-3f, r, 4.1666668e-2f);
    p = fmaf(p, r, 1.6666667e-1f);
    p = fmaf(p, r, 0.5f);
    p = fmaf(p, r, 1.0f);
    p = fmaf(p, r, 1.0f);
    return __int_as_float(__float_as_int(p) + (e << 23));
}
__device__ __forceinline__ float sigf(float x)  { return 1.0f / (1.0f + fexp(-x)); }
__device__ __forceinline__ float tanhf_(float x){ return fmaf(2.0f, sigf(2.0f * x), -1.0f); }

// ---------------- ptx helpers -------------------------------------------------
__device__ __forceinline__ uint32_t smem_u32(const void* p) {
    uint32_t a;
    asm("{ .reg .u64 t; cvta.to.shared.u64 t, %1; cvt.u32.u64 %0, t; }" : "=r"(a) : "l"(p));
    return a;
}
__device__ __forceinline__ void cpa16(uint32_t dst, const void* src, int valid) {
    asm volatile("cp.async.cg.shared.global [%0], [%1], 16, %2;"
                 :: "r"(dst), "l"(src), "r"(valid) : "memory");
}
#define CP_COMMIT()  asm volatile("cp.async.commit_group;" ::: "memory")
#define CP_WAIT(n)   asm volatile("cp.async.wait_group %0;" :: "n"(n) : "memory")

__device__ __forceinline__ void ldm4(uint32_t* r, uint32_t addr) {
    asm volatile("ldmatrix.sync.aligned.m8n8.x4.shared.b16 {%0,%1,%2,%3}, [%4];"
                 : "=r"(r[0]), "=r"(r[1]), "=r"(r[2]), "=r"(r[3]) : "r"(addr));
}
__device__ __forceinline__ void mma16816(float* d, const uint32_t* a, const uint32_t* b) {
    asm volatile(
        "mma.sync.aligned.m16n8k16.row.col.f32.f16.f16.f32 "
        "{%0,%1,%2,%3}, {%4,%5,%6,%7}, {%8,%9}, {%0,%1,%2,%3};"
        : "+f"(d[0]), "+f"(d[1]), "+f"(d[2]), "+f"(d[3])
        : "r"(a[0]), "r"(a[1]), "r"(a[2]), "r"(a[3]), "r"(b[0]), "r"(b[1]));
}
#define SW128(x) ((x) ^ (((x) >> 3) & 0x70))

// ---------------- init / gather / prep ---------------------------------------
__global__ void zero_state() {
    int idx = blockIdx.x * 256 + threadIdx.x;        // 131072 threads
    int b = idx >> 11, j = idx & 2047;
    fp16 z = __float2half_rn(0.0f);
    g_AbufH[idx] = z;
    g_AbufL[idx] = z;
    if (j < 1024) { g_c0[b * 1024 + j] = 0.f; g_c1[b * 1024 + j] = 0.f; }
    if (idx < BB) g_lossb[idx] = 0.f;
}

__global__ void gather_emb(const int* __restrict__ sent, const float* __restrict__ wordvec) {
    int idx = blockIdx.x * 256 + threadIdx.x;
    if (idx >= MROWS * KE) return;
    int r = idx / KE, k = idx - r * KE;
    int t = r >> 6, b = r & 63;
    float v = 0.f;
    if (k < EE) { int w = sent[b * TT + t]; v = wordvec[(size_t)w * EE + k]; }
    g_emb[idx] = __float2half_rn(v);
}

// transpose: W fp32 [Ksrc, Nsrc] -> O fp16 [Npad][Kpad] at col offset koff
__global__ void prep_T(const float* __restrict__ W, int Ksrc, int Nsrc,
                       fp16* __restrict__ O,
                       int Kpad, int koff, int Kspan, int Npad) {
    __shared__ float ts[32][33];
    int k0 = blockIdx.x * 32, n0 = blockIdx.y * 32;
    int tx = threadIdx.x, ty = threadIdx.y;
#pragma unroll
    for (int i = 0; i < 4; i++) {
        int k = k0 + ty + i * 8, n = n0 + tx;
        float v = (k < Ksrc && n < Nsrc) ? W[(size_t)k * Nsrc + n] : 0.f;
        ts[ty + i * 8][tx] = v;
    }
    __syncthreads();
#pragma unroll
    for (int i = 0; i < 4; i++) {
        int n = n0 + ty + i * 8, k = k0 + tx;
        if (n < Npad && k < Kspan)
            O[(size_t)n * Kpad + koff + k] = __float2half_rn(ts[tx][ty + i * 8]);
    }
}

// ---------------- fp16 GEMM via mma.sync --------------------------------------
// C[M,N] = A[M,K] @ B^T[N,K]   (A row-major, B stored [N][K])
// SPLITA=1: A given as hi+lo pair -> 2 MMA passes (h-quantization compensated)
// MT=2: CTA tile 128x128 (warps 2x4).  MT=1: CTA tile 64x128 (warps 1x8).
// mode 0: C[row*ldc+col] = acc + bias[col]  (row<Mreal, col<Nreal)
// mode 1: C[(z*64*MT+row)*ldc + col] = acc  (K-split partials)
template<int MT, int SPLITA>
__device__ __forceinline__ void ldstage(
    uint32_t st, int tid, int m0, int n0, int k0,
    const fp16* Ah, const fp16* Al, int lda,
    const fp16* B, int ldb, int Mreal)
{
    constexpr int AROWS  = MT * 64;
    constexpr int OFF_AL = AROWS * 128;
    constexpr int OFF_B  = AROWS * 128 * (1 + SPLITA);
#pragma unroll
    for (int e = tid; e < AROWS * 8; e += 256) {
        int r = e >> 3, c = e & 7;
        uint32_t sw = SW128((uint32_t)(r * 128 + c * 16));
        int gr = m0 + r;
        int ok = 16;
        if (MT == 2 && gr >= Mreal) { ok = 0; gr = 0; }
        size_t off = (size_t)gr * lda + k0 + c * 8;
        cpa16(st + sw, Ah + off, ok);
        if (SPLITA) cpa16(st + OFF_AL + sw, Al + off, ok);
    }
#pragma unroll
    for (int e = tid; e < 1024; e += 256) {
        int r = e >> 3, c = e & 7;
        uint32_t sw = SW128((uint32_t)(r * 128 + c * 16));
        size_t off = (size_t)(n0 + r) * ldb + k0 + c * 8;
        cpa16(st + OFF_B + sw, B + off, 16);
    }
}

template<int MT, int SPLITA>
__global__ __launch_bounds__(256, 1) void gemm_mma(
    const fp16* __restrict__ Ah, const fp16* __restrict__ Al, int lda,
    const fp16* __restrict__ B, int ldb,
    int kPerSplit, int Mreal, int Nreal,
    const float* __restrict__ bias, float* __restrict__ C, int ldc, int mode)
{
    extern __shared__ char smem[];
    constexpr int AROWS  = MT * 64;
    constexpr int OFF_AL = AROWS * 128;
    constexpr int OFF_B  = AROWS * 128 * (1 + SPLITA);
    constexpr int STAGE  = OFF_B + 16384;
    constexpr int NW     = MT * 16;          // warp n-width
    constexpr int NT     = 2 * MT;           // n8 tiles per warp

    int tid = threadIdx.x, lane = tid & 31, wid = tid >> 5;
    int wm = (MT == 2) ? (wid & 1) : 0;
    int wn = (MT == 2) ? (wid >> 1) : wid;
    int n0 = blockIdx.x * 128, m0 = blockIdx.y * AROWS;
    int kstart = blockIdx.z * kPerSplit;
    int nch = kPerSplit >> 6;

    uint32_t sb = smem_u32(smem);
    float acc[4][NT][4];
#pragma unroll
    for (int i = 0; i < 4; i++)
#pragma unroll
        for (int j = 0; j < NT; j++)
#pragma unroll
            for (int v = 0; v < 4; v++) acc[i][j][v] = 0.f;

    ldstage<MT, SPLITA>(sb, tid, m0, n0, kstart, Ah, Al, lda, B, ldb, Mreal);
    CP_COMMIT();

    for (int ic = 0; ic < nch; ic++) {
        uint32_t st = sb + (uint32_t)(ic & 1) * STAGE;
        if (ic + 1 < nch) {
            ldstage<MT, SPLITA>(sb + (uint32_t)((ic + 1) & 1) * STAGE, tid, m0, n0,
                                kstart + (ic + 1) * 64, Ah, Al, lda, B, ldb, Mreal);
            CP_COMMIT();
            CP_WAIT(1);
        } else {
            CP_WAIT(0);
        }
        __syncthreads();

#pragma unroll
        for (int q = 0; q < 4; q++) {
            uint32_t ah[4][4], al[4][4];
            int arow = wm * 64 + (lane & 15);
            int ach  = q * 32 + ((lane >> 4) << 4);
#pragma unroll
            for (int mt = 0; mt < 4; mt++) {
                uint32_t loc = SW128((uint32_t)((arow + mt * 16) * 128 + ach));
                ldm4(ah[mt], st + loc);
                if (SPLITA) ldm4(al[mt], st + OFF_AL + loc);
            }
            uint32_t bh[MT][4];
            int brow = wn * NW + (lane & 7) + (((lane >> 4) & 1) << 3);
            int bch  = q * 32 + (((lane >> 3) & 1) << 4);
#pragma unroll
            for (int p = 0; p < MT; p++) {
                uint32_t loc = SW128((uint32_t)((brow + p * 16) * 128 + bch));
                ldm4(bh[p], st + OFF_B + loc);
            }
#pragma unroll
            for (int mt = 0; mt < 4; mt++)
#pragma unroll
                for (int p = 0; p < MT; p++)
#pragma unroll
                    for (int h = 0; h < 2; h++) {
                        int nt = p * 2 + h;
                        mma16816(acc[mt][nt], ah[mt], &bh[p][h * 2]);
                        if (SPLITA) mma16816(acc[mt][nt], al[mt], &bh[p][h * 2]);
                    }
        }
        __syncthreads();
    }

    // epilogue
    int rbase = (mode ? blockIdx.z * AROWS : m0) + wm * 64 + (lane >> 2);
    int cbase = n0 + wn * NW + (lane & 3) * 2;
#pragma unroll
    for (int mt = 0; mt < 4; mt++)
#pragma unroll
        for (int nt = 0; nt < NT; nt++) {
            int col = cbase + nt * 8;
            int r0 = rbase + mt * 16;
            if (mode == 0) {
                if (col < Nreal) {
                    float ba = bias[col], bb = bias[col + 1];
                    if (r0 < Mreal) {
                        C[(size_t)r0 * ldc + col]     = acc[mt][nt][0] + ba;
                        C[(size_t)r0 * ldc + col + 1] = acc[mt][nt][1] + bb;
                    }
                    if (r0 + 8 < Mreal) {
                        C[(size_t)(r0 + 8) * ldc + col]     = acc[mt][nt][2] + ba;
                        C[(size_t)(r0 + 8) * ldc + col + 1] = acc[mt][nt][3] + bb;
                    }
                }
            } else {
                C[(size_t)r0 * ldc + col]           = acc[mt][nt][0];
                C[(size_t)r0 * ldc + col + 1]       = acc[mt][nt][1];
                C[(size_t)(r0 + 8) * ldc + col]     = acc[mt][nt][2];
                C[(size_t)(r0 + 8) * ldc + col + 1] = acc[mt][nt][3];
            }
        }
}

// ---------------- LSTM elementwise updates -----------------------------------
__global__ __launch_bounds__(256) void upd0(int t) {
    int idx = blockIdx.x * 256 + threadIdx.x;   // 65536
    int b = idx >> 10, h = idx & 1023;
    const float* pre = g_pre0 + ((size_t)(t * 64 + b)) * G4;
    float gi = pre[h], gf = pre[1024 + h], gg = pre[2048 + h], go = pre[3072 + h];
#pragma unroll
    for (int z = 0; z < 4; z++) {
        const float* gp = g_gp0 + ((size_t)(z * 64 + b)) * G4;
        gi += gp[h]; gf += gp[1024 + h]; gg += gp[2048 + h]; go += gp[3072 + h];
    }
    float c = sigf(gf) * g_c0[idx] + sigf(gi) * tanhf_(gg);
    float hn = sigf(go) * tanhf_(c);
    g_c0[idx] = c;
    fp16 hi = __float2half_rn(hn);
    g_AbufH[b * 2048 + h] = hi;
    g_AbufL[b * 2048 + h] = __float2half_rn(hn - __half2float(hi));
}

__global__ __launch_bounds__(256) void upd1(int t, const float* __restrict__ b1) {
    int idx = blockIdx.x * 256 + threadIdx.x;
    int b = idx >> 10, h = idx & 1023;
    float gi = b1[h], gf = b1[1024 + h], gg = b1[2048 + h], go = b1[3072 + h];
#pragma unroll
    for (int z = 0; z < 4; z++) {
        const float* gp = g_gp1 + ((size_t)(z * 64 + b)) * G4;
        gi += gp[h]; gf += gp[1024 + h]; gg += gp[2048 + h]; go += gp[3072 + h];
    }
    float c = sigf(gf) * g_c1[idx] + sigf(gi) * tanhf_(gg);
    float hn = sigf(go) * tanhf_(c);
    g_c1[idx] = c;
    fp16 hi = __float2half_rn(hn);
    g_AbufH[b * 2048 + 1024 + h] = hi;
    g_AbufL[b * 2048 + 1024 + h] = __float2half_rn(hn - __half2float(hi));
    g_H1[((size_t)b * TM1 + t) * HH + h] = hi;
}

// ---------------- loss --------------------------------------------------------
__global__ __launch_bounds__(256) void loss_row(const float* __restrict__ temp,
                                                const int* __restrict__ sent) {
    int t = blockIdx.x, b = blockIdx.y;
    const float* lg = temp + ((size_t)b * TM1 + t) * VV;
    __shared__ float buf[VV];
    __shared__ float red[8];
    __shared__ float s_mx;
    int tid = threadIdx.x;
    for (int i = tid; i < VV; i += 256) buf[i] = lg[i];
    __syncthreads();
    float m = -3.4e38f;
    for (int i = tid; i < VV; i += 256) m = fmaxf(m, buf[i]);
#pragma unroll
    for (int o = 16; o; o >>= 1) m = fmaxf(m, __shfl_xor_sync(0xffffffffu, m, o));
    if ((tid & 31) == 0) red[tid >> 5] = m;
    __syncthreads();
    if (tid == 0) {
        float v = red[0];
        for (int i = 1; i < 8; i++) v = fmaxf(v, red[i]);
        s_mx = v;
    }
    __syncthreads();
    float mx = s_mx;
    float s = 0.f;
    for (int i = tid; i < VV; i += 256) s += fexp(buf[i] - mx);
#pragma unroll
    for (int o = 16; o; o >>= 1) s += __shfl_xor_sync(0xffffffffu, s, o);
    if ((tid & 31) == 0) red[tid >> 5] = s;
    __syncthreads();
    if (tid == 0) {
        float v = 0.f;
        for (int i = 0; i < 8; i++) v += red[i];
        int gt = sent[b * TT + t + 1];
        if (gt != 0) {
            float lp = buf[gt] - (mx + logf(v));
            atomicAdd(&g_lossb[b], lp);
        }
    }
}

__global__ void loss_final(const int* __restrict__ length, float* __restrict__ out) {
    int tid = threadIdx.x;  // 64 threads
    float v = -g_lossb[tid] / (float)length[tid];
#pragma unroll
    for (int o = 16; o; o >>= 1) v += __shfl_xor_sync(0xffffffffu, v, o);
    __shared__ float r2[2];
    if ((tid & 31) == 0) r2[tid >> 5] = v;
    __syncthreads();
    if (tid == 0) out[0] = r2[0] + r2[1];
}

// ---------------- launch ------------------------------------------------------
#define SMEMG 65536   // both variants: 2 * 32768

extern "C" void kernel_launch(void* const* d_in, const int* in_sizes, int n_in,
                              void* d_out, int out_size) {
    const int*   sent    = (const int*)  d_in[0];
    const int*   length  = (const int*)  d_in[1];
    const float* wordvec = (const float*)d_in[2];
    const float* w_ih0   = (const float*)d_in[3];
    const float* w_hh0   = (const float*)d_in[4];
    const float* b0      = (const float*)d_in[5];
    const float* w_ih1   = (const float*)d_in[6];
    const float* w_hh1   = (const float*)d_in[7];
    const float* b1      = (const float*)d_in[8];
    const float* w_out   = (const float*)d_in[9];
    const float* b_out   = (const float*)d_in[10];
    float* out = (float*)d_out;

    long long tempoff = (long long)out_size - (long long)MROWS * VV;
    if (tempoff < 0) tempoff = 0;
    float* temp = out + tempoff;

    static int smem_set = 0;
    if (!smem_set) {
        cudaFuncSetAttribute(gemm_mma<1,1>, cudaFuncAttributeMaxDynamicSharedMemorySize, SMEMG);
        cudaFuncSetAttribute(gemm_mma<2,0>, cudaFuncAttributeMaxDynamicSharedMemorySize, SMEMG);
        smem_set = 1;
    }

    float *p_pre0, *p_gp0, *p_gp1;
    fp16 *p_emb, *p_AbH, *p_AbL, *p_H1;
    fp16 *p_wih0, *p_whh0, *p_w1, *p_wo;
    cudaGetSymbolAddress((void**)&p_pre0, g_pre0);
    cudaGetSymbolAddress((void**)&p_gp0,  g_gp0);
    cudaGetSymbolAddress((void**)&p_gp1,  g_gp1);
    cudaGetSymbolAddress((void**)&p_emb,  g_emb);
    cudaGetSymbolAddress((void**)&p_AbH,  g_AbufH);
    cudaGetSymbolAddress((void**)&p_AbL,  g_AbufL);
    cudaGetSymbolAddress((void**)&p_H1,   g_H1);
    cudaGetSymbolAddress((void**)&p_wih0, g_wih0T);
    cudaGetSymbolAddress((void**)&p_whh0, g_whh0T);
    cudaGetSymbolAddress((void**)&p_w1,   g_w1T);
    cudaGetSymbolAddress((void**)&p_wo,   g_woutT);

    zero_state<<<512, 256>>>();
    gather_emb<<<(MROWS * KE + 255) / 256, 256>>>(sent, wordvec);

    dim3 pth(32, 8);
    prep_T<<<dim3(KE / 32, G4 / 32), pth>>>(w_ih0, EE, G4, p_wih0, KE, 0, KE, G4);
    prep_T<<<dim3(HH / 32, G4 / 32), pth>>>(w_hh0, HH, G4, p_whh0, HH, 0, HH, G4);
    prep_T<<<dim3(HH / 32, G4 / 32), pth>>>(w_ih1, HH, G4, p_w1, 2048, 0, HH, G4);
    prep_T<<<dim3(HH / 32, G4 / 32), pth>>>(w_hh1, HH, G4, p_w1, 2048, 1024, HH, G4);
    prep_T<<<dim3(HH / 32, NPADV / 32), pth>>>(w_out, HH, VV, p_wo, HH, 0, HH, NPADV);

    // pre0 = emb @ w_ih0 + b0   [8128,320pad]@[320,4096]  (single-pass fp16)
    gemm_mma<2,0><<<dim3(G4 / 128, 64, 1), 256, SMEMG>>>(
        p_emb, nullptr, KE, p_wih0, KE, KE, MROWS, G4, b0, p_pre0, G4, 0);

    for (int t = 0; t < TM1; t++) {
        // layer0: gp0[z] = h0 @ w_hh0 (K-split 4 x 256, 2-pass split-A)
        gemm_mma<1,1><<<dim3(32, 1, 4), 256, SMEMG>>>(
            p_AbH, p_AbL, 2048, p_whh0, HH, 256, 64, G4, nullptr, p_gp0, G4, 1);
        upd0<<<256, 256>>>(t);
        // layer1: gp1[z] = [h0|h1] @ [w_ih1;w_hh1] (K-split 4 x 512)
        gemm_mma<1,1><<<dim3(32, 1, 4), 256, SMEMG>>>(
            p_AbH, p_AbL, 2048, p_w1, 2048, 512, 64, G4, nullptr, p_gp1, G4, 1);
        upd1<<<256, 256>>>(t, b1);
    }

    // logits = H1 @ w_out + b_out  [8128,1024]@[1024,10000pad]  (single-pass fp16)
    gemm_mma<2,0><<<dim3(NPADV / 128, 64, 1), 256, SMEMG>>>(
        p_H1, nullptr, HH, p_wo, HH, HH, MROWS, VV, b_out, temp, VV, 0);

    loss_row<<<dim3(TM1, BB), 256>>>(temp, sent);
    if (tempoff > 0) loss_final<<<1, 64>>>(length, out);
}